// round 2
// baseline (speedup 1.0000x reference)
#include <cuda_runtime.h>
#include <cstdint>

#define NUM_LABELS 64
#define MAXN (2 * 192 * 256 * 256)   // 25,165,824 — reference shape

// Scratch (allocation-free rule: __device__ globals)
__device__ float g_sums[NUM_LABELS];
__device__ int   g_cnts[NUM_LABELS];
__device__ float g_delta[NUM_LABELS];
__device__ unsigned char g_lab8[MAXN];   // compressed labels for the apply pass

// ---------------------------------------------------------------------------
// Kernel 0: zero accumulators (graph replays re-accumulate, must re-zero)
// ---------------------------------------------------------------------------
__global__ void zero_k() {
    int i = threadIdx.x;
    if (i < NUM_LABELS) { g_sums[i] = 0.0f; g_cnts[i] = 0; }
}

// ---------------------------------------------------------------------------
// Kernel 1: per-label sum+count, NO atomics.
// Per-thread private accumulators: acc[label*256 + tid], 64*256*8B = 128KB
// dynamic smem, one CTA per SM. Packed 64-bit entry:
//   entry += (float2ll_rn(v * 2^24) << 20) + 1
// count in low 20 bits (per-thread-label count ~41 avg << 2^20), fixed-point
// sum in upper 44 (|sum|*2^24 < 2^34). Exact decode at epilogue.
// Also writes labels compressed to 1 byte for the apply pass.
// ---------------------------------------------------------------------------
#define ACC_STEP(val, lbl)                                                    \
    acc[(lbl) * 256 + tid] +=                                                 \
        ((unsigned long long)(long long)__float2ll_rn((val) * 16777216.0f)    \
         << 20) + 1ull;

__global__ void __launch_bounds__(256) reduce_k(const float4* __restrict__ tex4,
                                                const int4*  __restrict__ lab4,
                                                int n4, int do_pack) {
    extern __shared__ unsigned long long acc[];   // [64][256]
    const int tid = threadIdx.x;

    #pragma unroll
    for (int i = tid; i < NUM_LABELS * 256; i += 256) acc[i] = 0ull;
    __syncthreads();

    unsigned int* lab8w = (unsigned int*)g_lab8;

    int i = blockIdx.x * 256 + tid;
    const int stride = gridDim.x * 256;

    // 4x unrolled, loads front-batched for MLP
    for (; i + 3 * stride < n4; i += 4 * stride) {
        const float4 t0 = tex4[i];
        const float4 t1 = tex4[i + stride];
        const float4 t2 = tex4[i + 2 * stride];
        const float4 t3 = tex4[i + 3 * stride];
        const int4 l0 = lab4[i];
        const int4 l1 = lab4[i + stride];
        const int4 l2 = lab4[i + 2 * stride];
        const int4 l3 = lab4[i + 3 * stride];

        if (do_pack) {
            lab8w[i]              = (unsigned)l0.x | ((unsigned)l0.y << 8) |
                                    ((unsigned)l0.z << 16) | ((unsigned)l0.w << 24);
            lab8w[i + stride]     = (unsigned)l1.x | ((unsigned)l1.y << 8) |
                                    ((unsigned)l1.z << 16) | ((unsigned)l1.w << 24);
            lab8w[i + 2 * stride] = (unsigned)l2.x | ((unsigned)l2.y << 8) |
                                    ((unsigned)l2.z << 16) | ((unsigned)l2.w << 24);
            lab8w[i + 3 * stride] = (unsigned)l3.x | ((unsigned)l3.y << 8) |
                                    ((unsigned)l3.z << 16) | ((unsigned)l3.w << 24);
        }

        ACC_STEP(t0.x, l0.x); ACC_STEP(t0.y, l0.y); ACC_STEP(t0.z, l0.z); ACC_STEP(t0.w, l0.w);
        ACC_STEP(t1.x, l1.x); ACC_STEP(t1.y, l1.y); ACC_STEP(t1.z, l1.z); ACC_STEP(t1.w, l1.w);
        ACC_STEP(t2.x, l2.x); ACC_STEP(t2.y, l2.y); ACC_STEP(t2.z, l2.z); ACC_STEP(t2.w, l2.w);
        ACC_STEP(t3.x, l3.x); ACC_STEP(t3.y, l3.y); ACC_STEP(t3.z, l3.z); ACC_STEP(t3.w, l3.w);
    }
    for (; i < n4; i += stride) {
        const float4 t = tex4[i];
        const int4   l = lab4[i];
        if (do_pack)
            lab8w[i] = (unsigned)l.x | ((unsigned)l.y << 8) |
                       ((unsigned)l.z << 16) | ((unsigned)l.w << 24);
        ACC_STEP(t.x, l.x); ACC_STEP(t.y, l.y); ACC_STEP(t.z, l.z); ACC_STEP(t.w, l.w);
    }
    __syncthreads();

    // Epilogue: thread l < 64 reduces its label's 256 slots.
    // Staggered slot index -> 2-phase (optimal) 64-bit LDS.
    if (tid < NUM_LABELS) {
        unsigned long long tot = 0ull;
        #pragma unroll 8
        for (int s = 0; s < 256; s++) {
            int sp = (s + tid) & 255;
            tot += acc[tid * 256 + sp];
        }
        unsigned int cnt = (unsigned int)(tot & 0xFFFFFull);
        long long fx = (long long)(tot - (unsigned long long)cnt) >> 20;
        atomicAdd(&g_sums[tid], (float)fx * (1.0f / 16777216.0f));
        atomicAdd(&g_cnts[tid], (int)cnt);
    }
}

// ---------------------------------------------------------------------------
// Kernel 2: per-label delta = mean - intensity (label 0 untouched)
// ---------------------------------------------------------------------------
__global__ void delta_k(const float* __restrict__ inten) {
    int l = threadIdx.x;
    if (l < NUM_LABELS) {
        float m = g_sums[l] / fmaxf((float)g_cnts[l], 1.0f);
        g_delta[l] = (l > 0) ? (m - inten[l]) : 0.0f;
    }
}

// ---------------------------------------------------------------------------
// Kernel 3a: out = tex - delta[lab], labels read as packed bytes (25MB not 100MB)
// ---------------------------------------------------------------------------
__global__ void __launch_bounds__(256) apply_packed_k(const float4* __restrict__ tex4,
                                                      float4* __restrict__ out4,
                                                      int n4) {
    __shared__ float sd[NUM_LABELS];
    if (threadIdx.x < NUM_LABELS) sd[threadIdx.x] = g_delta[threadIdx.x];
    __syncthreads();

    int i = blockIdx.x * 256 + threadIdx.x;
    if (i < n4) {
        const float4 t = tex4[i];
        const unsigned int l = ((const unsigned int*)g_lab8)[i];
        float4 o;
        o.x = t.x - sd[l & 0xFF];
        o.y = t.y - sd[(l >> 8) & 0xFF];
        o.z = t.z - sd[(l >> 16) & 0xFF];
        o.w = t.w - sd[l >> 24];
        out4[i] = o;
    }
}

// ---------------------------------------------------------------------------
// Kernel 3b: fallback apply reading int32 labels (n not 4-divisible / > MAXN)
// ---------------------------------------------------------------------------
__global__ void __launch_bounds__(256) apply_scalar_k(const float* __restrict__ tex,
                                                      const int*  __restrict__ lab,
                                                      float* __restrict__ out,
                                                      int n) {
    __shared__ float sd[NUM_LABELS];
    if (threadIdx.x < NUM_LABELS) sd[threadIdx.x] = g_delta[threadIdx.x];
    __syncthreads();
    int i = blockIdx.x * 256 + threadIdx.x;
    if (i < n) out[i] = tex[i] - sd[lab[i]];
}

// Fallback reduction (scalar, shared-atomic) for shapes not handled fast-path
__global__ void __launch_bounds__(256) reduce_scalar_k(const float* __restrict__ tex,
                                                       const int*  __restrict__ lab,
                                                       int n) {
    __shared__ unsigned long long acc[8][NUM_LABELS];
    const int w = threadIdx.x >> 5;
    for (int i = threadIdx.x; i < 8 * NUM_LABELS; i += 256) (&acc[0][0])[i] = 0ull;
    __syncthreads();
    int i = blockIdx.x * 256 + threadIdx.x;
    const int stride = gridDim.x * 256;
    for (; i < n; i += stride) {
        atomicAdd(&acc[w][lab[i]],
                  ((unsigned long long)(long long)__float2ll_rn(tex[i] * 16777216.0f) << 20) + 1ull);
    }
    __syncthreads();
    for (int l = threadIdx.x; l < NUM_LABELS; l += 256) {
        unsigned long long tot = 0ull;
        #pragma unroll
        for (int ww = 0; ww < 8; ww++) tot += acc[ww][l];
        unsigned int cnt = (unsigned int)(tot & 0xFFFFFull);
        long long fx = (long long)(tot - (unsigned long long)cnt) >> 20;
        atomicAdd(&g_sums[l], (float)fx * (1.0f / 16777216.0f));
        atomicAdd(&g_cnts[l], (int)cnt);
    }
}

// ---------------------------------------------------------------------------
extern "C" void kernel_launch(void* const* d_in, const int* in_sizes, int n_in,
                              void* d_out, int out_size) {
    const float* tex   = (const float*)d_in[0];
    const int*   lab   = (const int*)  d_in[1];
    const float* inten = (const float*)d_in[2];
    float* out = (float*)d_out;

    const int n  = in_sizes[0];
    const int n4 = n >> 2;
    const bool fast = ((n & 3) == 0) && (n <= MAXN);

    zero_k<<<1, 64>>>();

    if (fast) {
        static int smem_set = 0;   // host-side config, not work-determinism
        const int smem_bytes = NUM_LABELS * 256 * (int)sizeof(unsigned long long); // 128KB
        if (!smem_set) {
            cudaFuncSetAttribute(reduce_k, cudaFuncAttributeMaxDynamicSharedMemorySize,
                                 smem_bytes);
            smem_set = 1;
        }
        reduce_k<<<148, 256, smem_bytes>>>((const float4*)tex, (const int4*)lab, n4, 1);
        delta_k<<<1, 64>>>(inten);
        int app_blocks = (n4 + 255) / 256;
        apply_packed_k<<<app_blocks, 256>>>((const float4*)tex, (float4*)out, n4);
    } else {
        reduce_scalar_k<<<1184, 256>>>(tex, lab, n);
        delta_k<<<1, 64>>>(inten);
        int app_blocks = (n + 255) / 256;
        apply_scalar_k<<<app_blocks, 256>>>(tex, lab, out, n);
    }
}

// round 3
// speedup vs baseline: 1.1100x; 1.1100x over previous
#include <cuda_runtime.h>
#include <cstdint>

#define NUM_LABELS 64
#define MAXN (2 * 192 * 256 * 256)   // 25,165,824 — reference shape

// Scratch (allocation-free rule: __device__ globals)
__device__ float g_sums[NUM_LABELS];
__device__ int   g_cnts[NUM_LABELS];
__device__ float g_delta[NUM_LABELS];
__device__ unsigned char g_lab8[MAXN];   // compressed labels for the apply pass

// ---------------------------------------------------------------------------
// Kernel 0: zero accumulators (graph replays re-accumulate, must re-zero)
// ---------------------------------------------------------------------------
__global__ void zero_k() {
    int i = threadIdx.x;
    if (i < NUM_LABELS) { g_sums[i] = 0.0f; g_cnts[i] = 0; }
}

// ---------------------------------------------------------------------------
// Kernel 1: per-label sum+count, NO atomics, NO converts.
// Per-thread private float2 accumulators: acc[label*256 + tid] = {sum, count}.
// 64*256*8B = 128KB dynamic smem, 1 CTA/SM, grid = 148 (one wave).
// Each element: LDS.64 -> FADD, FADD(+1) -> STS.64, all cheap pipes.
// Bank-conflict-free: addr = l*2048 + tid*8 -> bank depends only on tid.
// Also writes labels compressed to 1 byte for the apply pass.
// ---------------------------------------------------------------------------
#define UNROLL 8

__global__ void __launch_bounds__(256) reduce_k(const float4* __restrict__ tex4,
                                                const int4*  __restrict__ lab4,
                                                int n4) {
    extern __shared__ float2 acc[];   // [64][256]
    const int tid = threadIdx.x;

    #pragma unroll
    for (int i = tid; i < NUM_LABELS * 256; i += 256)
        acc[i] = make_float2(0.0f, 0.0f);
    __syncthreads();

    unsigned int* lab8w = (unsigned int*)g_lab8;

    int i = blockIdx.x * 256 + tid;
    const int stride = gridDim.x * 256;

    // 8x unrolled, all 16 LDG.128 front-batched for MLP
    for (; i + (UNROLL - 1) * stride < n4; i += UNROLL * stride) {
        float4 t[UNROLL];
        int4   l[UNROLL];
        #pragma unroll
        for (int u = 0; u < UNROLL; u++) t[u] = tex4[i + u * stride];
        #pragma unroll
        for (int u = 0; u < UNROLL; u++) l[u] = lab4[i + u * stride];

        #pragma unroll
        for (int u = 0; u < UNROLL; u++) {
            lab8w[i + u * stride] = (unsigned)l[u].x | ((unsigned)l[u].y << 8) |
                                    ((unsigned)l[u].z << 16) | ((unsigned)l[u].w << 24);
            float2 a;
            a = acc[l[u].x * 256 + tid]; a.x += t[u].x; a.y += 1.0f; acc[l[u].x * 256 + tid] = a;
            a = acc[l[u].y * 256 + tid]; a.x += t[u].y; a.y += 1.0f; acc[l[u].y * 256 + tid] = a;
            a = acc[l[u].z * 256 + tid]; a.x += t[u].z; a.y += 1.0f; acc[l[u].z * 256 + tid] = a;
            a = acc[l[u].w * 256 + tid]; a.x += t[u].w; a.y += 1.0f; acc[l[u].w * 256 + tid] = a;
        }
    }
    for (; i < n4; i += stride) {
        const float4 t = tex4[i];
        const int4   l = lab4[i];
        lab8w[i] = (unsigned)l.x | ((unsigned)l.y << 8) |
                   ((unsigned)l.z << 16) | ((unsigned)l.w << 24);
        float2 a;
        a = acc[l.x * 256 + tid]; a.x += t.x; a.y += 1.0f; acc[l.x * 256 + tid] = a;
        a = acc[l.y * 256 + tid]; a.x += t.y; a.y += 1.0f; acc[l.y * 256 + tid] = a;
        a = acc[l.z * 256 + tid]; a.x += t.z; a.y += 1.0f; acc[l.z * 256 + tid] = a;
        a = acc[l.w * 256 + tid]; a.x += t.w; a.y += 1.0f; acc[l.w * 256 + tid] = a;
    }
    __syncthreads();

    // Epilogue: thread l < 64 reduces its label's 256 slots (staggered, conflict-free)
    if (tid < NUM_LABELS) {
        float s = 0.0f, c = 0.0f;
        #pragma unroll 8
        for (int k = 0; k < 256; k++) {
            int sp = (k + tid) & 255;
            float2 v = acc[tid * 256 + sp];
            s += v.x; c += v.y;
        }
        atomicAdd(&g_sums[tid], s);
        atomicAdd(&g_cnts[tid], (int)c);
    }
}

// ---------------------------------------------------------------------------
// Kernel 2: per-label delta = mean - intensity (label 0 untouched)
// ---------------------------------------------------------------------------
__global__ void delta_k(const float* __restrict__ inten) {
    int l = threadIdx.x;
    if (l < NUM_LABELS) {
        float m = g_sums[l] / fmaxf((float)g_cnts[l], 1.0f);
        g_delta[l] = (l > 0) ? (m - inten[l]) : 0.0f;
    }
}

// ---------------------------------------------------------------------------
// Kernel 3a: out = tex - delta[lab], labels read as packed bytes (25MB not 100MB)
// ---------------------------------------------------------------------------
__global__ void __launch_bounds__(256) apply_packed_k(const float4* __restrict__ tex4,
                                                      float4* __restrict__ out4,
                                                      int n4) {
    __shared__ float sd[NUM_LABELS];
    if (threadIdx.x < NUM_LABELS) sd[threadIdx.x] = g_delta[threadIdx.x];
    __syncthreads();

    int i = blockIdx.x * 256 + threadIdx.x;
    if (i < n4) {
        const float4 t = tex4[i];
        const unsigned int l = ((const unsigned int*)g_lab8)[i];
        float4 o;
        o.x = t.x - sd[l & 0xFF];
        o.y = t.y - sd[(l >> 8) & 0xFF];
        o.z = t.z - sd[(l >> 16) & 0xFF];
        o.w = t.w - sd[l >> 24];
        out4[i] = o;
    }
}

// ---------------------------------------------------------------------------
// Fallback path (n not 4-divisible or > MAXN): scalar, shared-atomic
// ---------------------------------------------------------------------------
__global__ void __launch_bounds__(256) reduce_scalar_k(const float* __restrict__ tex,
                                                       const int*  __restrict__ lab,
                                                       int n) {
    __shared__ float2 accw[8][NUM_LABELS];
    const int w = threadIdx.x >> 5;
    for (int i = threadIdx.x; i < 8 * NUM_LABELS; i += 256)
        (&accw[0][0])[i] = make_float2(0.0f, 0.0f);
    __syncthreads();
    int i = blockIdx.x * 256 + threadIdx.x;
    const int stride = gridDim.x * 256;
    for (; i < n; i += stride) {
        atomicAdd(&accw[w][lab[i]].x, tex[i]);
        atomicAdd(&accw[w][lab[i]].y, 1.0f);
    }
    __syncthreads();
    for (int l = threadIdx.x; l < NUM_LABELS; l += 256) {
        float s = 0.0f, c = 0.0f;
        #pragma unroll
        for (int ww = 0; ww < 8; ww++) { s += accw[ww][l].x; c += accw[ww][l].y; }
        atomicAdd(&g_sums[l], s);
        atomicAdd(&g_cnts[l], (int)c);
    }
}

__global__ void __launch_bounds__(256) apply_scalar_k(const float* __restrict__ tex,
                                                      const int*  __restrict__ lab,
                                                      float* __restrict__ out,
                                                      int n) {
    __shared__ float sd[NUM_LABELS];
    if (threadIdx.x < NUM_LABELS) sd[threadIdx.x] = g_delta[threadIdx.x];
    __syncthreads();
    int i = blockIdx.x * 256 + threadIdx.x;
    if (i < n) out[i] = tex[i] - sd[lab[i]];
}

// ---------------------------------------------------------------------------
extern "C" void kernel_launch(void* const* d_in, const int* in_sizes, int n_in,
                              void* d_out, int out_size) {
    const float* tex   = (const float*)d_in[0];
    const int*   lab   = (const int*)  d_in[1];
    const float* inten = (const float*)d_in[2];
    float* out = (float*)d_out;

    const int n  = in_sizes[0];
    const int n4 = n >> 2;
    const bool fast = ((n & 3) == 0) && (n <= MAXN);

    zero_k<<<1, 64>>>();

    if (fast) {
        static int smem_set = 0;   // host-side one-time config
        const int smem_bytes = NUM_LABELS * 256 * (int)sizeof(float2); // 128KB
        if (!smem_set) {
            cudaFuncSetAttribute(reduce_k, cudaFuncAttributeMaxDynamicSharedMemorySize,
                                 smem_bytes);
            smem_set = 1;
        }
        reduce_k<<<148, 256, smem_bytes>>>((const float4*)tex, (const int4*)lab, n4);
        delta_k<<<1, 64>>>(inten);
        int app_blocks = (n4 + 255) / 256;
        apply_packed_k<<<app_blocks, 256>>>((const float4*)tex, (float4*)out, n4);
    } else {
        reduce_scalar_k<<<1184, 256>>>(tex, lab, n);
        delta_k<<<1, 64>>>(inten);
        int app_blocks = (n + 255) / 256;
        apply_scalar_k<<<app_blocks, 256>>>(tex, lab, out, n);
    }
}